// round 1
// baseline (speedup 1.0000x reference)
#include <cuda_runtime.h>
#include <cstdint>

#define Bc   2
#define Lc   2048
#define Dc   2048
#define Hc   16
#define KVHc 8
#define Dhc  128
#define HDc  2048   // H*Dh
#define KVDc 1024   // KVH*Dh
#define D3c  6144   // 3*D
#define EPSc 1e-5f

// ---------------- scratch (device globals: allocation-guard safe) -------------
__device__ float g_mod[Bc * D3c];                      // shift|scale|gate per batch
__device__ float g_xm[(size_t)Bc * Lc * Dc];           // modulated normed input
__device__ float g_q [(size_t)Bc * Lc * HDc];
__device__ float g_k [(size_t)Bc * Lc * KVDc];
__device__ float g_v [(size_t)Bc * Lc * KVDc];
__device__ float g_o [(size_t)Bc * Lc * HDc];

// ---------------- kernel 1: mod = silu(temb) @ w_mod + b_mod ------------------
__global__ void k_mod(const float* __restrict__ temb,
                      const float* __restrict__ w_mod,
                      const float* __restrict__ b_mod) {
    __shared__ float st[Dc];
    int b = blockIdx.y;
    int j = blockIdx.x * 256 + threadIdx.x;         // 0..6143
    for (int i = threadIdx.x; i < Dc; i += 256) {
        float x = temb[b * Dc + i];
        st[i] = x / (1.f + __expf(-x));
    }
    __syncthreads();
    float acc = b_mod[j];
#pragma unroll 4
    for (int i = 0; i < Dc; i++)
        acc = fmaf(st[i], w_mod[(size_t)i * D3c + j], acc);
    g_mod[b * D3c + j] = acc;
}

// ---------------- kernel 2: xm = rmsnorm(x)*w_ln*(1+scale)+shift ---------------
__global__ void k_rmsmod(const float* __restrict__ x,
                         const float* __restrict__ w_ln) {
    int row = blockIdx.x;            // b*L + l
    int b   = row >> 11;             // row / L
    const float* xr = x + (size_t)row * Dc;
    int tid = threadIdx.x;

    float ss = 0.f;
    for (int i = tid; i < Dc; i += 256) { float v = xr[i]; ss = fmaf(v, v, ss); }
#pragma unroll
    for (int o = 16; o; o >>= 1) ss += __shfl_xor_sync(0xffffffffu, ss, o);

    __shared__ float red[8];
    __shared__ float sinv;
    if ((tid & 31) == 0) red[tid >> 5] = ss;
    __syncthreads();
    if (tid == 0) {
        float t = 0.f;
#pragma unroll
        for (int w = 0; w < 8; w++) t += red[w];
        sinv = rsqrtf(t * (1.f / Dc) + EPSc);
    }
    __syncthreads();
    float inv = sinv;
    const float* sh = g_mod + b * D3c;          // shift
    const float* sc = sh + Dc;                  // scale
    float* xm = g_xm + (size_t)row * Dc;
    for (int i = tid; i < Dc; i += 256)
        xm[i] = fmaf(xr[i] * inv * w_ln[i], 1.f + sc[i], sh[i]);
}

// ---------------- kernel 3: SGEMM 128x128x8, double-buffered -------------------
// C[M,N] = A[M,K] @ B[K,N].  EPI=1: C = hid + gate[b]*acc (final projection).
template<int EPI>
__global__ void __launch_bounds__(256)
k_sgemm(const float* __restrict__ A, const float* __restrict__ Bm,
        float* __restrict__ C, int M, int N, int K,
        const float* __restrict__ hid) {
    __shared__ float As[2][8][128];
    __shared__ float Bs[2][8][128];
    int tid = threadIdx.x;
    int tx = tid & 15, ty = tid >> 4;
    int bx = blockIdx.x, by = blockIdx.y;

    int ar = tid >> 1, ac = (tid & 1) << 2;     // A: 128 rows x 8 cols
    int br = tid >> 5, bc = (tid & 31) << 2;    // B: 8 rows x 128 cols
    const float* Ap = A  + (size_t)(by * 128 + ar) * K + ac;
    const float* Bp = Bm + (size_t)br * N + bx * 128 + bc;
    int nk = K >> 3;

    { // prologue
        float4 a = *(const float4*)Ap;
        float4 bv = *(const float4*)Bp;
        As[0][ac + 0][ar] = a.x; As[0][ac + 1][ar] = a.y;
        As[0][ac + 2][ar] = a.z; As[0][ac + 3][ar] = a.w;
        *(float4*)&Bs[0][br][bc] = bv;
    }
    __syncthreads();

    float acc[8][8];
#pragma unroll
    for (int i = 0; i < 8; i++)
#pragma unroll
        for (int j = 0; j < 8; j++) acc[i][j] = 0.f;

    int buf = 0;
    for (int kb = 0; kb < nk; kb++) {
        float4 an, bn;
        bool more = (kb + 1 < nk);
        if (more) {
            an = *(const float4*)(Ap + (kb + 1) * 8);
            bn = *(const float4*)(Bp + (size_t)(kb + 1) * 8 * N);
        }
#pragma unroll
        for (int kk = 0; kk < 8; kk++) {
            float4 a0 = *(const float4*)&As[buf][kk][ty * 8];
            float4 a1 = *(const float4*)&As[buf][kk][ty * 8 + 4];
            float4 b0 = *(const float4*)&Bs[buf][kk][tx * 8];
            float4 b1 = *(const float4*)&Bs[buf][kk][tx * 8 + 4];
            float av[8] = {a0.x, a0.y, a0.z, a0.w, a1.x, a1.y, a1.z, a1.w};
            float bw[8] = {b0.x, b0.y, b0.z, b0.w, b1.x, b1.y, b1.z, b1.w};
#pragma unroll
            for (int i = 0; i < 8; i++)
#pragma unroll
                for (int j = 0; j < 8; j++)
                    acc[i][j] = fmaf(av[i], bw[j], acc[i][j]);
        }
        if (more) {
            As[buf ^ 1][ac + 0][ar] = an.x; As[buf ^ 1][ac + 1][ar] = an.y;
            As[buf ^ 1][ac + 2][ar] = an.z; As[buf ^ 1][ac + 3][ar] = an.w;
            *(float4*)&Bs[buf ^ 1][br][bc] = bn;
        }
        __syncthreads();
        buf ^= 1;
    }

#pragma unroll
    for (int i = 0; i < 8; i++) {
        int row = by * 128 + ty * 8 + i;
        size_t off = (size_t)row * N + bx * 128 + tx * 8;
        if (EPI == 0) {
            *(float4*)(C + off)     = make_float4(acc[i][0], acc[i][1], acc[i][2], acc[i][3]);
            *(float4*)(C + off + 4) = make_float4(acc[i][4], acc[i][5], acc[i][6], acc[i][7]);
        } else {
            int b = row >> 11;
            const float* g = g_mod + b * D3c + 2 * Dc + bx * 128 + tx * 8;
            float o[8];
#pragma unroll
            for (int j = 0; j < 8; j++)
                o[j] = fmaf(g[j], acc[i][j], hid[off + j]);
            *(float4*)(C + off)     = make_float4(o[0], o[1], o[2], o[3]);
            *(float4*)(C + off + 4) = make_float4(o[4], o[5], o[6], o[7]);
        }
    }
}

// ---------------- kernel 4: per-head RMSNorm + mixed RoPE ----------------------
// one warp per (b,l,head) vector of 128; heads 0..15 = q, 16..23 = k.
__global__ void __launch_bounds__(256)
k_qknorm_rope(const float* __restrict__ cos1d, const float* __restrict__ sin1d,
              const float* __restrict__ rope3d,
              const float* __restrict__ qn, const float* __restrict__ kn,
              const int* __restrict__ mp) {
    int warp = threadIdx.x >> 5, lane = threadIdx.x & 31;
    int v  = blockIdx.x * 8 + warp;      // 0 .. 98303
    int bl = v / 24, r = v % 24;
    int b = bl >> 11, l = bl & 2047;

    float* ptr; const float* w;
    if (r < Hc) { ptr = g_q + (size_t)bl * HDc  + r * Dhc;        w = qn; }
    else        { ptr = g_k + (size_t)bl * KVDc + (r - Hc) * Dhc; w = kn; }

    float val[4];
    float ss = 0.f;
#pragma unroll
    for (int i = 0; i < 4; i++) { val[i] = ptr[lane + 32 * i]; ss = fmaf(val[i], val[i], ss); }
#pragma unroll
    for (int o = 16; o; o >>= 1) ss += __shfl_xor_sync(0xffffffffu, ss, o);
    float inv = rsqrtf(ss * (1.f / Dhc) + EPSc);
#pragma unroll
    for (int i = 0; i < 4; i++) val[i] *= inv * w[lane + 32 * i];

    // modality masks. Detect int64 vs int32 storage: values are small positive,
    // so int64 little-endian => mp[1]==0; int32 => mp[1]==1025 != 0.
    bool is64 = (mp[1] == 0);
    bool in_full = false, in_img = false; int rel = 0;
#pragma unroll
    for (int m = 0; m < 2; m++) {
        int off, ln;
        if (is64) { off = mp[(b * 4 + m * 2) * 2]; ln = mp[(b * 4 + m * 2 + 1) * 2]; }
        else      { off = mp[b * 4 + m * 2];       ln = mp[b * 4 + m * 2 + 1]; }
        int seg_end = off + max(ln, 1);
        if (l >= off && l < seg_end) in_full = true;
        if (l >= off + 1 && l < off + ln) { in_img = true; rel += l - (off + 1); }
    }
    bool text = !in_full;
    bool img  = in_img && (rel < 1024);
    rel = min(max(rel, 0), 1023);

    float out[4];
    if (text) {
#pragma unroll
        for (int i = 0; i < 4; i++) {
            int d = lane + 32 * i;
            float c = cos1d[l * Dhc + d], s = sin1d[l * Dhc + d];
            float rot = (i < 2) ? -val[i ^ 2] : val[i ^ 2];
            out[i] = fmaf(val[i], c, rot * s);
        }
    } else {
        // warp-uniform branch: shfl legal
#pragma unroll
        for (int i = 0; i < 4; i++) {
            int d = lane + 32 * i; int p = d >> 1; int jj = d & 1;
            float partner = __shfl_xor_sync(0xffffffffu, val[i], 1);
            float q0 = jj ? partner : val[i];
            float q1 = jj ? val[i] : partner;
            const float* R = rope3d + ((size_t)rel * 64 + p) * 4;
            float oimg = fmaf(q0, R[jj], q1 * R[2 + jj]);
            out[i] = img ? oimg : val[i];
        }
    }
#pragma unroll
    for (int i = 0; i < 4; i++) ptr[lane + 32 * i] = out[i];
}

// ---------------- kernel 5: flash attention, Tq=64, Tk=64 ----------------------
__global__ void __launch_bounds__(256)
k_flash(const float* __restrict__ gq, const float* __restrict__ gk,
        const float* __restrict__ gv, float* __restrict__ go) {
    extern __shared__ float sm[];
    float* Qt = sm;                  // [128][68] transposed: Qt[kk][qrow]
    float* Kt = sm + 128 * 68;       // [128][68] transposed; unioned with Vs[64][128]
    float* Ps = sm + 2 * 128 * 68;   // [64][65]

    int tid = threadIdx.x;
    int tx = tid & 15, ty = tid >> 4;
    int q0 = blockIdx.x << 6;
    int h  = blockIdx.y, b = blockIdx.z;
    int kh = h >> 1;                         // GQA repeat=2
    const float SCALE = 0.08838834764831845f; // 1/sqrt(128)

    const float* qbase = gq + (size_t)(b * Lc + q0) * HDc + h * Dhc;
#pragma unroll
    for (int it = 0; it < 8; it++) {
        int idx = tid + (it << 8);
        int r = idx >> 5, c4 = (idx & 31) << 2;
        float4 v = *(const float4*)(qbase + (size_t)r * HDc + c4);
        Qt[(c4 + 0) * 68 + r] = v.x; Qt[(c4 + 1) * 68 + r] = v.y;
        Qt[(c4 + 2) * 68 + r] = v.z; Qt[(c4 + 3) * 68 + r] = v.w;
    }

    float mI[4], lI[4], O[4][8];
#pragma unroll
    for (int i = 0; i < 4; i++) {
        mI[i] = -1e30f; lI[i] = 0.f;
#pragma unroll
        for (int c = 0; c < 8; c++) O[i][c] = 0.f;
    }

    for (int kt = 0; kt < Lc / 64; kt++) {
        __syncthreads();  // Qt ready (kt=0) / prev PV done before Kt overwrite
        const float* kbase = gk + (size_t)(b * Lc + (kt << 6)) * KVDc + kh * Dhc;
#pragma unroll
        for (int it = 0; it < 8; it++) {
            int idx = tid + (it << 8);
            int r = idx >> 5, c4 = (idx & 31) << 2;
            float4 v = *(const float4*)(kbase + (size_t)r * KVDc + c4);
            Kt[(c4 + 0) * 68 + r] = v.x; Kt[(c4 + 1) * 68 + r] = v.y;
            Kt[(c4 + 2) * 68 + r] = v.z; Kt[(c4 + 3) * 68 + r] = v.w;
        }
        __syncthreads();

        float s[4][4];
#pragma unroll
        for (int i = 0; i < 4; i++)
#pragma unroll
            for (int j = 0; j < 4; j++) s[i][j] = 0.f;
#pragma unroll 4
        for (int kk = 0; kk < 128; kk++) {
            float4 q4 = *(const float4*)&Qt[kk * 68 + (ty << 2)];
            float4 k4 = *(const float4*)&Kt[kk * 68 + (tx << 2)];
            float qa[4] = {q4.x, q4.y, q4.z, q4.w};
            float ka[4] = {k4.x, k4.y, k4.z, k4.w};
#pragma unroll
            for (int i = 0; i < 4; i++)
#pragma unroll
                for (int j = 0; j < 4; j++)
                    s[i][j] = fmaf(qa[i], ka[j], s[i][j]);
        }

#pragma unroll
        for (int i = 0; i < 4; i++) {
            float rmax = -1e30f;
#pragma unroll
            for (int j = 0; j < 4; j++) { s[i][j] *= SCALE; rmax = fmaxf(rmax, s[i][j]); }
#pragma unroll
            for (int o = 8; o; o >>= 1)
                rmax = fmaxf(rmax, __shfl_xor_sync(0xffffffffu, rmax, o));
            float mnew = fmaxf(mI[i], rmax);
            float psum = 0.f;
#pragma unroll
            for (int j = 0; j < 4; j++) {
                float p = __expf(s[i][j] - mnew);
                Ps[(ty * 4 + i) * 65 + tx * 4 + j] = p;
                psum += p;
            }
#pragma unroll
            for (int o = 8; o; o >>= 1)
                psum += __shfl_xor_sync(0xffffffffu, psum, o);
            float corr = __expf(mI[i] - mnew);
            lI[i] = lI[i] * corr + psum;
            mI[i] = mnew;
#pragma unroll
            for (int c = 0; c < 8; c++) O[i][c] *= corr;
        }
        __syncthreads();   // Ps written, Kt reads done -> safe to overwrite as Vs

        float* Vs = Kt;    // [64][128] row-major
        const float* vbase = gv + (size_t)(b * Lc + (kt << 6)) * KVDc + kh * Dhc;
#pragma unroll
        for (int it = 0; it < 8; it++) {
            int idx = tid + (it << 8);
            int r = idx >> 5, c4 = (idx & 31) << 2;
            *(float4*)&Vs[(r << 7) + c4] = *(const float4*)(vbase + (size_t)r * KVDc + c4);
        }
        __syncthreads();

#pragma unroll 4
        for (int j = 0; j < 64; j++) {
            float4 v0 = *(const float4*)&Vs[(j << 7) + (tx << 3)];
            float4 v1 = *(const float4*)&Vs[(j << 7) + (tx << 3) + 4];
#pragma unroll
            for (int i = 0; i < 4; i++) {
                float p = Ps[(ty * 4 + i) * 65 + j];
                O[i][0] = fmaf(p, v0.x, O[i][0]); O[i][1] = fmaf(p, v0.y, O[i][1]);
                O[i][2] = fmaf(p, v0.z, O[i][2]); O[i][3] = fmaf(p, v0.w, O[i][3]);
                O[i][4] = fmaf(p, v1.x, O[i][4]); O[i][5] = fmaf(p, v1.y, O[i][5]);
                O[i][6] = fmaf(p, v1.z, O[i][6]); O[i][7] = fmaf(p, v1.w, O[i][7]);
            }
        }
    }

#pragma unroll
    for (int i = 0; i < 4; i++) {
        float inv = 1.f / lI[i];
        float* op = go + (size_t)(b * Lc + q0 + ty * 4 + i) * HDc + h * Dhc + (tx << 3);
        *(float4*)op       = make_float4(O[i][0] * inv, O[i][1] * inv, O[i][2] * inv, O[i][3] * inv);
        *(float4*)(op + 4) = make_float4(O[i][4] * inv, O[i][5] * inv, O[i][6] * inv, O[i][7] * inv);
    }
}

// ---------------- launch -------------------------------------------------------
extern "C" void kernel_launch(void* const* d_in, const int* in_sizes, int n_in,
                              void* d_out, int out_size) {
    const float* hidden = (const float*)d_in[0];
    const float* temb   = (const float*)d_in[1];
    const float* w_ln   = (const float*)d_in[2];
    const float* w_mod  = (const float*)d_in[3];
    const float* b_mod  = (const float*)d_in[4];
    const float* wq     = (const float*)d_in[5];
    const float* wk     = (const float*)d_in[6];
    const float* wv     = (const float*)d_in[7];
    const float* wo     = (const float*)d_in[8];
    const float* qn     = (const float*)d_in[9];
    const float* kn     = (const float*)d_in[10];
    const float* cos1   = (const float*)d_in[11];
    const float* sin1   = (const float*)d_in[12];
    const float* rope3  = (const float*)d_in[13];
    const int*   mpos   = (const int*)d_in[14];
    float* out = (float*)d_out;

    void *pxm, *pq, *pk, *pv, *po;
    cudaGetSymbolAddress(&pxm, g_xm);
    cudaGetSymbolAddress(&pq,  g_q);
    cudaGetSymbolAddress(&pk,  g_k);
    cudaGetSymbolAddress(&pv,  g_v);
    cudaGetSymbolAddress(&po,  g_o);

    k_mod<<<dim3(D3c / 256, Bc), 256>>>(temb, w_mod, b_mod);
    k_rmsmod<<<Bc * Lc, 256>>>(hidden, w_ln);

    k_sgemm<0><<<dim3(16, 32), 256>>>((const float*)pxm, wq, (float*)pq,
                                      Bc * Lc, HDc,  Dc, nullptr);
    k_sgemm<0><<<dim3(8, 32), 256>>>((const float*)pxm, wk, (float*)pk,
                                     Bc * Lc, KVDc, Dc, nullptr);
    k_sgemm<0><<<dim3(8, 32), 256>>>((const float*)pxm, wv, (float*)pv,
                                     Bc * Lc, KVDc, Dc, nullptr);

    k_qknorm_rope<<<(Bc * Lc * (Hc + KVHc)) / 8, 256>>>(cos1, sin1, rope3, qn, kn, mpos);

    size_t fsm = (size_t)(2 * 128 * 68 + 64 * 65) * sizeof(float);   // 86272 B
    cudaFuncSetAttribute(k_flash, cudaFuncAttributeMaxDynamicSharedMemorySize, (int)fsm);
    k_flash<<<dim3(Lc / 64, Hc, Bc), 256, fsm>>>((const float*)pq, (const float*)pk,
                                                 (const float*)pv, (float*)po);

    k_sgemm<1><<<dim3(16, 32), 256>>>((const float*)po, wo, out,
                                      Bc * Lc, Dc, HDc, hidden);
}

// round 3
// speedup vs baseline: 1.4341x; 1.4341x over previous
#include <cuda_runtime.h>
#include <cstdint>

#define Bc   2
#define Lc   2048
#define Dc   2048
#define Hc   16
#define KVHc 8
#define Dhc  128
#define QKVN 4096
#define D3c  6144
#define EPSc 1e-5f

// ---------------- scratch (device globals: allocation-guard safe) -------------
__device__ float g_mod[Bc * D3c];
__device__ float g_xm [(size_t)Bc * Lc * Dc];
__device__ float g_qkv[(size_t)Bc * Lc * QKVN];   // 0..2047 Q | 2048..3071 K | 3072..4095 V
__device__ float g_o  [(size_t)Bc * Lc * Dc];
__device__ float g_wT [(size_t)QKVN * Dc];        // [wq^T ; wk^T ; wv^T], K-contig rows
__device__ float g_woT[(size_t)Dc * Dc];

__device__ __forceinline__ float to_tf32(float v) {
    uint32_t u; asm("cvt.rna.tf32.f32 %0, %1;" : "=r"(u) : "f"(v));
    return __uint_as_float(u);
}
__device__ __forceinline__ void mma8(float* d, const uint4& a, uint32_t b0, uint32_t b1) {
    asm volatile("mma.sync.aligned.m16n8k8.row.col.f32.tf32.tf32.f32 "
                 "{%0,%1,%2,%3}, {%4,%5,%6,%7}, {%8,%9}, {%0,%1,%2,%3};"
                 : "+f"(d[0]), "+f"(d[1]), "+f"(d[2]), "+f"(d[3])
                 : "r"(a.x), "r"(a.y), "r"(a.z), "r"(a.w), "r"(b0), "r"(b1));
}

// ================= kernel 1: mod = silu(temb) @ w_mod + b_mod =================
__global__ void k_mod(const float* __restrict__ temb, const float* __restrict__ w_mod,
                      const float* __restrict__ b_mod) {
    __shared__ float st[Dc];
    int b = blockIdx.y;
    int j = blockIdx.x * 256 + threadIdx.x;
    for (int i = threadIdx.x; i < Dc; i += 256) {
        float x = temb[b * Dc + i];
        st[i] = x / (1.f + __expf(-x));
    }
    __syncthreads();
    float acc = b_mod[j];
#pragma unroll 4
    for (int i = 0; i < Dc; i++) acc = fmaf(st[i], w_mod[(size_t)i * D3c + j], acc);
    g_mod[b * D3c + j] = acc;
}

// ====== kernel 2: xm = tf32(rmsnorm(x)*w_ln*(1+scale)+shift) ==================
__global__ void k_rmsmod(const float* __restrict__ x, const float* __restrict__ w_ln) {
    int row = blockIdx.x;
    int b   = row >> 11;
    const float* xr = x + (size_t)row * Dc;
    int tid = threadIdx.x;
    float ss = 0.f;
    for (int i = tid; i < Dc; i += 256) { float v = xr[i]; ss = fmaf(v, v, ss); }
#pragma unroll
    for (int o = 16; o; o >>= 1) ss += __shfl_xor_sync(0xffffffffu, ss, o);
    __shared__ float red[8];
    __shared__ float sinv;
    if ((tid & 31) == 0) red[tid >> 5] = ss;
    __syncthreads();
    if (tid == 0) {
        float t = 0.f;
#pragma unroll
        for (int w = 0; w < 8; w++) t += red[w];
        sinv = rsqrtf(t * (1.f / Dc) + EPSc);
    }
    __syncthreads();
    float inv = sinv;
    const float* sh = g_mod + b * D3c;
    const float* sc = sh + Dc;
    float* xm = g_xm + (size_t)row * Dc;
    for (int i = tid; i < Dc; i += 256)
        xm[i] = to_tf32(fmaf(xr[i] * inv * w_ln[i], 1.f + sc[i], sh[i]));
}

// ====== transpose src[K][N] (N-contig) -> dst[N][K] (K-contig), round tf32 ====
__global__ void k_transpose(const float* __restrict__ src, float* __restrict__ dst,
                            int K, int N) {
    __shared__ float t[32][33];
    int kb = blockIdx.y * 32, nb = blockIdx.x * 32;
    int x = threadIdx.x, y = threadIdx.y;
#pragma unroll
    for (int i = 0; i < 32; i += 8)
        t[y + i][x] = src[(size_t)(kb + y + i) * N + nb + x];
    __syncthreads();
#pragma unroll
    for (int i = 0; i < 32; i += 8)
        dst[(size_t)(nb + y + i) * K + kb + x] = to_tf32(t[x][y + i]);
}

// ====== tf32 mma.sync GEMM: C[M,N] = A[M,K] @ Bt[N,K]^T ========================
// Tiles: BM=128, BN=256, BK=32. 8 warps, warp tile 64x64 (4 m-frags x 8 n-frags).
// Smem in fragment order: each m16n8k8 fragment = 32 lanes x 16B, one LDS.128.
#define MMASMEM (24576 * 4)   // 96 KB: A 2x4096 floats, B 2x8192 floats

template<int EPI>
__global__ void __launch_bounds__(256, 1)
k_mma(const float* __restrict__ Ag, const float* __restrict__ Bg,
      float* __restrict__ C, int N, int K, const float* __restrict__ hid) {
    extern __shared__ float smf[];
    float* Asm = smf;          // buf*4096
    float* Bsm = smf + 8192;   // buf*8192

    int t = threadIdx.x, lane = t & 31, wid = t >> 5;
    int wm = wid >> 2, wn = wid & 3;
    int m0 = blockIdx.y * 128, n0 = blockIdx.x * 256;

    // staging constants
    int r0 = t >> 3;                 // 0..31
    int kb = (t & 7) * 4;            // 0..28
    int ch = (kb >> 2) & 1;
    int ks = kb >> 3;                // 0..3
    int half = ks & 1, kp = ks >> 1;
    int Abase = (ks * 8 + (r0 >> 4)) * 128 + (r0 & 7) * 16 + ((r0 & 15) >> 3) + 2 * ch;
    int Bbase = (kp * 32 + (r0 >> 3)) * 128 + (r0 & 7) * 16 + half * 2 + ch;

    const float* Aptr = Ag + (size_t)(m0 + r0) * K + kb;
    const float* Bptr = Bg + (size_t)(n0 + r0) * K + kb;

    float acc[4][8][4];
#pragma unroll
    for (int i = 0; i < 4; i++)
#pragma unroll
        for (int j = 0; j < 8; j++)
#pragma unroll
            for (int c = 0; c < 4; c++) acc[i][j][c] = 0.f;

    float4 pa[4], pb[8];
    // prologue: tile 0
#pragma unroll
    for (int p = 0; p < 4; p++) pa[p] = *(const float4*)(Aptr + (size_t)(p * 32) * K);
#pragma unroll
    for (int p = 0; p < 8; p++) pb[p] = *(const float4*)(Bptr + (size_t)(p * 32) * K);
#pragma unroll
    for (int p = 0; p < 4; p++) {
        Asm[Abase + p * 256 + 0] = pa[p].x; Asm[Abase + p * 256 + 4] = pa[p].y;
        Asm[Abase + p * 256 + 8] = pa[p].z; Asm[Abase + p * 256 + 12] = pa[p].w;
    }
#pragma unroll
    for (int p = 0; p < 8; p++) {
        Bsm[Bbase + p * 512 + 0] = pb[p].x; Bsm[Bbase + p * 512 + 4] = pb[p].y;
        Bsm[Bbase + p * 512 + 8] = pb[p].z; Bsm[Bbase + p * 512 + 12] = pb[p].w;
    }
    __syncthreads();

    int nk = K >> 5;
    int buf = 0;
    for (int kt = 0; kt < nk; kt++) {
        bool more = (kt + 1 < nk);
        if (more) {
            const float* Ap = Aptr + (kt + 1) * 32;
            const float* Bp = Bptr + (kt + 1) * 32;
#pragma unroll
            for (int p = 0; p < 4; p++) pa[p] = *(const float4*)(Ap + (size_t)(p * 32) * K);
#pragma unroll
            for (int p = 0; p < 8; p++) pb[p] = *(const float4*)(Bp + (size_t)(p * 32) * K);
        }

        const float* Ab = Asm + buf * 4096;
        const float* Bb = Bsm + buf * 8192;
#pragma unroll
        for (int kpp = 0; kpp < 2; kpp++) {
            uint4 bb[8];
#pragma unroll
            for (int j = 0; j < 8; j++)
                bb[j] = *(const uint4*)(Bb + (kpp * 32 + wn * 8 + j) * 128 + lane * 4);
#pragma unroll
            for (int hh = 0; hh < 2; hh++) {
                uint4 aa[4];
#pragma unroll
                for (int i = 0; i < 4; i++)
                    aa[i] = *(const uint4*)(Ab + ((kpp * 2 + hh) * 8 + wm * 4 + i) * 128 + lane * 4);
#pragma unroll
                for (int i = 0; i < 4; i++)
#pragma unroll
                    for (int j = 0; j < 8; j++)
                        mma8(acc[i][j], aa[i],
                             hh ? bb[j].z : bb[j].x,
                             hh ? bb[j].w : bb[j].y);
            }
        }

        if (more) {
            float* Ab2 = Asm + (buf ^ 1) * 4096;
            float* Bb2 = Bsm + (buf ^ 1) * 8192;
#pragma unroll
            for (int p = 0; p < 4; p++) {
                Ab2[Abase + p * 256 + 0] = pa[p].x; Ab2[Abase + p * 256 + 4] = pa[p].y;
                Ab2[Abase + p * 256 + 8] = pa[p].z; Ab2[Abase + p * 256 + 12] = pa[p].w;
            }
#pragma unroll
            for (int p = 0; p < 8; p++) {
                Bb2[Bbase + p * 512 + 0] = pb[p].x; Bb2[Bbase + p * 512 + 4] = pb[p].y;
                Bb2[Bbase + p * 512 + 8] = pb[p].z; Bb2[Bbase + p * 512 + 12] = pb[p].w;
            }
        }
        __syncthreads();
        buf ^= 1;
    }

    // epilogue: c0=(r,c) c1=(r,c+1) c2=(r+8,c) c3=(r+8,c+1); r=lane>>2, c=2*(lane&3)
#pragma unroll
    for (int i = 0; i < 4; i++) {
        int gm = m0 + (wm * 4 + i) * 16 + (lane >> 2);
#pragma unroll
        for (int j = 0; j < 8; j++) {
            int gn = n0 + (wn * 8 + j) * 8 + 2 * (lane & 3);
            size_t o0 = (size_t)gm * N + gn;
            size_t o1 = (size_t)(gm + 8) * N + gn;
            if (EPI == 0) {
                *(float2*)(C + o0) = make_float2(acc[i][j][0], acc[i][j][1]);
                *(float2*)(C + o1) = make_float2(acc[i][j][2], acc[i][j][3]);
            } else {
                int b0 = gm >> 11, b1 = (gm + 8) >> 11;
                float2 h0 = *(const float2*)(hid + o0);
                float2 h1 = *(const float2*)(hid + o1);
                float2 g0 = *(const float2*)(g_mod + b0 * D3c + 2 * Dc + gn);
                float2 g1 = *(const float2*)(g_mod + b1 * D3c + 2 * Dc + gn);
                *(float2*)(C + o0) = make_float2(fmaf(g0.x, acc[i][j][0], h0.x),
                                                 fmaf(g0.y, acc[i][j][1], h0.y));
                *(float2*)(C + o1) = make_float2(fmaf(g1.x, acc[i][j][2], h1.x),
                                                 fmaf(g1.y, acc[i][j][3], h1.y));
            }
        }
    }
}

// ====== per-head RMSNorm + mixed RoPE (fused qkv layout, stride 4096) =========
__global__ void __launch_bounds__(256)
k_qknorm_rope(const float* __restrict__ cos1d, const float* __restrict__ sin1d,
              const float* __restrict__ rope3d,
              const float* __restrict__ qn, const float* __restrict__ kn,
              const int* __restrict__ mp) {
    int warp = threadIdx.x >> 5, lane = threadIdx.x & 31;
    int v  = blockIdx.x * 8 + warp;
    int bl = v / 24, r = v % 24;
    int b = bl >> 11, l = bl & 2047;

    float* ptr; const float* w;
    if (r < Hc) { ptr = g_qkv + (size_t)bl * QKVN + r * Dhc;               w = qn; }
    else        { ptr = g_qkv + (size_t)bl * QKVN + 2048 + (r - Hc) * Dhc; w = kn; }

    float val[4];
    float ss = 0.f;
#pragma unroll
    for (int i = 0; i < 4; i++) { val[i] = ptr[lane + 32 * i]; ss = fmaf(val[i], val[i], ss); }
#pragma unroll
    for (int o = 16; o; o >>= 1) ss += __shfl_xor_sync(0xffffffffu, ss, o);
    float inv = rsqrtf(ss * (1.f / Dhc) + EPSc);
#pragma unroll
    for (int i = 0; i < 4; i++) val[i] *= inv * w[lane + 32 * i];

    bool is64 = (mp[1] == 0);
    bool in_full = false, in_img = false; int rel = 0;
#pragma unroll
    for (int m = 0; m < 2; m++) {
        int off, ln;
        if (is64) { off = mp[(b * 4 + m * 2) * 2]; ln = mp[(b * 4 + m * 2 + 1) * 2]; }
        else      { off = mp[b * 4 + m * 2];       ln = mp[b * 4 + m * 2 + 1]; }
        int seg_end = off + max(ln, 1);
        if (l >= off && l < seg_end) in_full = true;
        if (l >= off + 1 && l < off + ln) { in_img = true; rel += l - (off + 1); }
    }
    bool text = !in_full;
    bool img  = in_img && (rel < 1024);
    rel = min(max(rel, 0), 1023);

    float out[4];
    if (text) {
#pragma unroll
        for (int i = 0; i < 4; i++) {
            int d = lane + 32 * i;
            float c = cos1d[l * Dhc + d], s = sin1d[l * Dhc + d];
            float rot = (i < 2) ? -val[i ^ 2] : val[i ^ 2];
            out[i] = fmaf(val[i], c, rot * s);
        }
    } else {
#pragma unroll
        for (int i = 0; i < 4; i++) {
            int d = lane + 32 * i; int p = d >> 1; int jj = d & 1;
            float partner = __shfl_xor_sync(0xffffffffu, val[i], 1);
            float q0 = jj ? partner : val[i];
            float q1 = jj ? val[i] : partner;
            const float* R = rope3d + ((size_t)rel * 64 + p) * 4;
            float oimg = fmaf(q0, R[jj], q1 * R[2 + jj]);
            out[i] = img ? oimg : val[i];
        }
    }
#pragma unroll
    for (int i = 0; i < 4; i++) ptr[lane + 32 * i] = out[i];
}

// ====== flash attention (fp32 FFMA), reads fused qkv ==========================
__global__ void __launch_bounds__(256)
k_flash(float* __restrict__ go) {
    extern __shared__ float sm[];
    float* Qt = sm;
    float* Kt = sm + 128 * 68;
    float* Ps = sm + 2 * 128 * 68;

    int tid = threadIdx.x;
    int tx = tid & 15, ty = tid >> 4;
    int q0 = blockIdx.x << 6;
    int h  = blockIdx.y, b = blockIdx.z;
    int kh = h >> 1;
    const float SCALE = 0.08838834764831845f;

    const float* qbase = g_qkv + (size_t)(b * Lc + q0) * QKVN + h * Dhc;
#pragma unroll
    for (int it = 0; it < 8; it++) {
        int idx = tid + (it << 8);
        int r = idx >> 5, c4 = (idx & 31) << 2;
        float4 v = *(const float4*)(qbase + (size_t)r * QKVN + c4);
        Qt[(c4 + 0) * 68 + r] = v.x; Qt[(c4 + 1) * 68 + r] = v.y;
        Qt[(c4 + 2) * 68 + r] = v.z; Qt[(c4 + 3) * 68 + r] = v.w;
    }

    float mI[4], lI[4], O[4][8];
#pragma unroll
    for (int i = 0; i < 4; i++) {
        mI[i] = -1e30f; lI[i] = 0.f;
#pragma unroll
        for (int c = 0; c < 8; c++) O[i][c] = 0.f;
    }

    for (int kt = 0; kt < Lc / 64; kt++) {
        __syncthreads();
        const float* kbase = g_qkv + (size_t)(b * Lc + (kt << 6)) * QKVN + 2048 + kh * Dhc;
#pragma unroll
        for (int it = 0; it < 8; it++) {
            int idx = tid + (it << 8);
            int r = idx >> 5, c4 = (idx & 31) << 2;
            float4 v = *(const float4*)(kbase + (size_t)r * QKVN + c4);
            Kt[(c4 + 0) * 68 + r] = v.x; Kt[(c4 + 1) * 68 + r] = v.y;
            Kt[(c4 + 2) * 68 + r] = v.z; Kt[(c4 + 3) * 68 + r] = v.w;
        }
        __syncthreads();

        float s[4][4];
#pragma unroll
        for (int i = 0; i < 4; i++)
#pragma unroll
            for (int j = 0; j < 4; j++) s[i][j] = 0.f;
#pragma unroll 4
        for (int kk = 0; kk < 128; kk++) {
            float4 q4 = *(const float4*)&Qt[kk * 68 + (ty << 2)];
            float4 k4 = *(const float4*)&Kt[kk * 68 + (tx << 2)];
            float qa[4] = {q4.x, q4.y, q4.z, q4.w};
            float ka[4] = {k4.x, k4.y, k4.z, k4.w};
#pragma unroll
            for (int i = 0; i < 4; i++)
#pragma unroll
                for (int j = 0; j < 4; j++)
                    s[i][j] = fmaf(qa[i], ka[j], s[i][j]);
        }

#pragma unroll
        for (int i = 0; i < 4; i++) {
            float rmax = -1e30f;
#pragma unroll
            for (int j = 0; j < 4; j++) { s[i][j] *= SCALE; rmax = fmaxf(rmax, s[i][j]); }
#pragma unroll
            for (int o = 8; o; o >>= 1)
                rmax = fmaxf(rmax, __shfl_xor_sync(0xffffffffu, rmax, o));
            float mnew = fmaxf(mI[i], rmax);
            float psum = 0.f;
#pragma unroll
            for (int j = 0; j < 4; j++) {
                float p = __expf(s[i][j] - mnew);
                Ps[(ty * 4 + i) * 65 + tx * 4 + j] = p;
                psum += p;
            }
#pragma unroll
            for (int o = 8; o; o >>= 1)
                psum += __shfl_xor_sync(0xffffffffu, psum, o);
            float corr = __expf(mI[i] - mnew);
            lI[i] = lI[i] * corr + psum;
            mI[i] = mnew;
#pragma unroll
            for (int c = 0; c < 8; c++) O[i][c] *= corr;
        }
        __syncthreads();

        float* Vs = Kt;
        const float* vbase = g_qkv + (size_t)(b * Lc + (kt << 6)) * QKVN + 3072 + kh * Dhc;
#pragma unroll
        for (int it = 0; it < 8; it++) {
            int idx = tid + (it << 8);
            int r = idx >> 5, c4 = (idx & 31) << 2;
            *(float4*)&Vs[(r << 7) + c4] = *(const float4*)(vbase + (size_t)r * QKVN + c4);
        }
        __syncthreads();

#pragma unroll 4
        for (int j = 0; j < 64; j++) {
            float4 v0 = *(const float4*)&Vs[(j << 7) + (tx << 3)];
            float4 v1 = *(const float4*)&Vs[(j << 7) + (tx << 3) + 4];
#pragma unroll
            for (int i = 0; i < 4; i++) {
                float p = Ps[(ty * 4 + i) * 65 + j];
                O[i][0] = fmaf(p, v0.x, O[i][0]); O[i][1] = fmaf(p, v0.y, O[i][1]);
                O[i][2] = fmaf(p, v0.z, O[i][2]); O[i][3] = fmaf(p, v0.w, O[i][3]);
                O[i][4] = fmaf(p, v1.x, O[i][4]); O[i][5] = fmaf(p, v1.y, O[i][5]);
                O[i][6] = fmaf(p, v1.z, O[i][6]); O[i][7] = fmaf(p, v1.w, O[i][7]);
            }
        }
    }

#pragma unroll
    for (int i = 0; i < 4; i++) {
        float inv = 1.f / lI[i];
        float* op = go + (size_t)(b * Lc + q0 + ty * 4 + i) * Dc + h * Dhc + (tx << 3);
        *(float4*)op = make_float4(to_tf32(O[i][0]*inv), to_tf32(O[i][1]*inv),
                                   to_tf32(O[i][2]*inv), to_tf32(O[i][3]*inv));
        *(float4*)(op + 4) = make_float4(to_tf32(O[i][4]*inv), to_tf32(O[i][5]*inv),
                                         to_tf32(O[i][6]*inv), to_tf32(O[i][7]*inv));
    }
}

// ================================ host ========================================
extern "C" void kernel_launch(void* const* d_in, const int* in_sizes, int n_in,
                              void* d_out, int out_size) {
    const float* hidden = (const float*)d_in[0];
    const float* temb   = (const float*)d_in[1];
    const float* w_ln   = (const float*)d_in[2];
    const float* w_mod  = (const float*)d_in[3];
    const float* b_mod  = (const float*)d_in[4];
    const float* wq     = (const float*)d_in[5];
    const float* wk     = (const float*)d_in[6];
    const float* wv     = (const float*)d_in[7];
    const float* wo     = (const float*)d_in[8];
    const float* qn     = (const float*)d_in[9];
    const float* kn     = (const float*)d_in[10];
    const float* cos1   = (const float*)d_in[11];
    const float* sin1   = (const float*)d_in[12];
    const float* rope3  = (const float*)d_in[13];
    const int*   mpos   = (const int*)d_in[14];
    float* out = (float*)d_out;

    void *pxm, *pqkv, *po, *pwT, *pwoT;
    cudaGetSymbolAddress(&pxm,  g_xm);
    cudaGetSymbolAddress(&pqkv, g_qkv);
    cudaGetSymbolAddress(&po,   g_o);
    cudaGetSymbolAddress(&pwT,  g_wT);
    cudaGetSymbolAddress(&pwoT, g_woT);

    cudaFuncSetAttribute(k_mma<0>, cudaFuncAttributeMaxDynamicSharedMemorySize, MMASMEM);
    cudaFuncSetAttribute(k_mma<1>, cudaFuncAttributeMaxDynamicSharedMemorySize, MMASMEM);

    k_mod<<<dim3(D3c / 256, Bc), 256>>>(temb, w_mod, b_mod);
    k_rmsmod<<<Bc * Lc, 256>>>(hidden, w_ln);

    k_transpose<<<dim3(Dc / 32, Dc / 32), dim3(32, 8)>>>(wq, (float*)pwT, Dc, Dc);
    k_transpose<<<dim3(1024 / 32, Dc / 32), dim3(32, 8)>>>(wk, (float*)pwT + (size_t)2048 * Dc, Dc, 1024);
    k_transpose<<<dim3(1024 / 32, Dc / 32), dim3(32, 8)>>>(wv, (float*)pwT + (size_t)3072 * Dc, Dc, 1024);
    k_transpose<<<dim3(Dc / 32, Dc / 32), dim3(32, 8)>>>(wo, (float*)pwoT, Dc, Dc);

    // fused QKV GEMM: [4096 x 4096] = xm @ [wq|wk|wv]^T
    k_mma<0><<<dim3(QKVN / 256, (Bc * Lc) / 128), 256, MMASMEM>>>(
        (const float*)pxm, (const float*)pwT, (float*)pqkv, QKVN, Dc, nullptr);

    k_qknorm_rope<<<(Bc * Lc * (Hc + KVHc)) / 8, 256>>>(cos1, sin1, rope3, qn, kn, mpos);

    size_t fsm = (size_t)(2 * 128 * 68 + 64 * 65) * sizeof(float);
    cudaFuncSetAttribute(k_flash, cudaFuncAttributeMaxDynamicSharedMemorySize, (int)fsm);
    k_flash<<<dim3(Lc / 64, Hc, Bc), 256, fsm>>>((float*)po);

    // output projection + residual/gate epilogue
    k_mma<1><<<dim3(Dc / 256, (Bc * Lc) / 128), 256, MMASMEM>>>(
        (const float*)po, (const float*)pwoT, out, Dc, Dc, hidden);
}

// round 4
// speedup vs baseline: 2.2211x; 1.5488x over previous
#include <cuda_runtime.h>
#include <cstdint>

#define Bc   2
#define Lc   2048
#define Dc   2048
#define Hc   16
#define KVHc 8
#define Dhc  128
#define QKVN 4096
#define D3c  6144
#define EPSc 1e-5f

// ---------------- scratch (device globals: allocation-guard safe) -------------
__device__ float g_mod[Bc * D3c];
__device__ float g_xm [(size_t)Bc * Lc * Dc];
__device__ float g_qkv[(size_t)Bc * Lc * QKVN];   // 0..2047 Q | 2048..3071 K | 3072..4095 V
__device__ float g_o  [(size_t)Bc * Lc * Dc];
__device__ float g_wT [(size_t)QKVN * Dc];
__device__ float g_woT[(size_t)Dc * Dc];

__device__ __forceinline__ float to_tf32(float v) {
    uint32_t u; asm("cvt.rna.tf32.f32 %0, %1;" : "=r"(u) : "f"(v));
    return __uint_as_float(u);
}
__device__ __forceinline__ void mma8(float* d, const uint4& a, uint32_t b0, uint32_t b1) {
    asm volatile("mma.sync.aligned.m16n8k8.row.col.f32.tf32.tf32.f32 "
                 "{%0,%1,%2,%3}, {%4,%5,%6,%7}, {%8,%9}, {%0,%1,%2,%3};"
                 : "+f"(d[0]), "+f"(d[1]), "+f"(d[2]), "+f"(d[3])
                 : "r"(a.x), "r"(a.y), "r"(a.z), "r"(a.w), "r"(b0), "r"(b1));
}

// ================= kernel 1: mod = silu(temb) @ w_mod + b_mod =================
__global__ void k_mod(const float* __restrict__ temb, const float* __restrict__ w_mod,
                      const float* __restrict__ b_mod) {
    __shared__ float st[Dc];
    int b = blockIdx.y;
    int j = blockIdx.x * 256 + threadIdx.x;
    for (int i = threadIdx.x; i < Dc; i += 256) {
        float x = temb[b * Dc + i];
        st[i] = x / (1.f + __expf(-x));
    }
    __syncthreads();
    float acc = b_mod[j];
#pragma unroll 4
    for (int i = 0; i < Dc; i++) acc = fmaf(st[i], w_mod[(size_t)i * D3c + j], acc);
    g_mod[b * D3c + j] = acc;
}

// ====== kernel 2: xm = tf32(rmsnorm(x)*w_ln*(1+scale)+shift) ==================
__global__ void k_rmsmod(const float* __restrict__ x, const float* __restrict__ w_ln) {
    int row = blockIdx.x;
    int b   = row >> 11;
    const float* xr = x + (size_t)row * Dc;
    int tid = threadIdx.x;
    float ss = 0.f;
    for (int i = tid; i < Dc; i += 256) { float v = xr[i]; ss = fmaf(v, v, ss); }
#pragma unroll
    for (int o = 16; o; o >>= 1) ss += __shfl_xor_sync(0xffffffffu, ss, o);
    __shared__ float red[8];
    __shared__ float sinv;
    if ((tid & 31) == 0) red[tid >> 5] = ss;
    __syncthreads();
    if (tid == 0) {
        float t = 0.f;
#pragma unroll
        for (int w = 0; w < 8; w++) t += red[w];
        sinv = rsqrtf(t * (1.f / Dc) + EPSc);
    }
    __syncthreads();
    float inv = sinv;
    const float* sh = g_mod + b * D3c;
    const float* sc = sh + Dc;
    float* xm = g_xm + (size_t)row * Dc;
    for (int i = tid; i < Dc; i += 256)
        xm[i] = to_tf32(fmaf(xr[i] * inv * w_ln[i], 1.f + sc[i], sh[i]));
}

// ====== transpose src[K][N] -> dst[N][K], round tf32 ==========================
__global__ void k_transpose(const float* __restrict__ src, float* __restrict__ dst,
                            int K, int N) {
    __shared__ float t[32][33];
    int kb = blockIdx.y * 32, nb = blockIdx.x * 32;
    int x = threadIdx.x, y = threadIdx.y;
#pragma unroll
    for (int i = 0; i < 32; i += 8)
        t[y + i][x] = src[(size_t)(kb + y + i) * N + nb + x];
    __syncthreads();
#pragma unroll
    for (int i = 0; i < 32; i += 8)
        dst[(size_t)(nb + y + i) * K + kb + x] = to_tf32(t[x][y + i]);
}

// ====== tf32 mma.sync GEMM: C[M,N] = A[M,K] @ Bt[N,K]^T (round-3, verified) ===
#define MMASMEM (24576 * 4)

template<int EPI>
__global__ void __launch_bounds__(256, 1)
k_mma(const float* __restrict__ Ag, const float* __restrict__ Bg,
      float* __restrict__ C, int N, int K, const float* __restrict__ hid) {
    extern __shared__ float smf[];
    float* Asm = smf;
    float* Bsm = smf + 8192;

    int t = threadIdx.x, lane = t & 31, wid = t >> 5;
    int wm = wid >> 2, wn = wid & 3;
    int m0 = blockIdx.y * 128, n0 = blockIdx.x * 256;

    int r0 = t >> 3;
    int kb = (t & 7) * 4;
    int ch = (kb >> 2) & 1;
    int ks = kb >> 3;
    int half = ks & 1, kp = ks >> 1;
    int Abase = (ks * 8 + (r0 >> 4)) * 128 + (r0 & 7) * 16 + ((r0 & 15) >> 3) + 2 * ch;
    int Bbase = (kp * 32 + (r0 >> 3)) * 128 + (r0 & 7) * 16 + half * 2 + ch;

    const float* Aptr = Ag + (size_t)(m0 + r0) * K + kb;
    const float* Bptr = Bg + (size_t)(n0 + r0) * K + kb;

    float acc[4][8][4];
#pragma unroll
    for (int i = 0; i < 4; i++)
#pragma unroll
        for (int j = 0; j < 8; j++)
#pragma unroll
            for (int c = 0; c < 4; c++) acc[i][j][c] = 0.f;

    float4 pa[4], pb[8];
#pragma unroll
    for (int p = 0; p < 4; p++) pa[p] = *(const float4*)(Aptr + (size_t)(p * 32) * K);
#pragma unroll
    for (int p = 0; p < 8; p++) pb[p] = *(const float4*)(Bptr + (size_t)(p * 32) * K);
#pragma unroll
    for (int p = 0; p < 4; p++) {
        Asm[Abase + p * 256 + 0] = pa[p].x; Asm[Abase + p * 256 + 4] = pa[p].y;
        Asm[Abase + p * 256 + 8] = pa[p].z; Asm[Abase + p * 256 + 12] = pa[p].w;
    }
#pragma unroll
    for (int p = 0; p < 8; p++) {
        Bsm[Bbase + p * 512 + 0] = pb[p].x; Bsm[Bbase + p * 512 + 4] = pb[p].y;
        Bsm[Bbase + p * 512 + 8] = pb[p].z; Bsm[Bbase + p * 512 + 12] = pb[p].w;
    }
    __syncthreads();

    int nk = K >> 5;
    int buf = 0;
    for (int kt = 0; kt < nk; kt++) {
        bool more = (kt + 1 < nk);
        if (more) {
            const float* Ap = Aptr + (kt + 1) * 32;
            const float* Bp = Bptr + (kt + 1) * 32;
#pragma unroll
            for (int p = 0; p < 4; p++) pa[p] = *(const float4*)(Ap + (size_t)(p * 32) * K);
#pragma unroll
            for (int p = 0; p < 8; p++) pb[p] = *(const float4*)(Bp + (size_t)(p * 32) * K);
        }

        const float* Ab = Asm + buf * 4096;
        const float* Bb = Bsm + buf * 8192;
#pragma unroll
        for (int kpp = 0; kpp < 2; kpp++) {
            uint4 bb[8];
#pragma unroll
            for (int j = 0; j < 8; j++)
                bb[j] = *(const uint4*)(Bb + (kpp * 32 + wn * 8 + j) * 128 + lane * 4);
#pragma unroll
            for (int hh = 0; hh < 2; hh++) {
                uint4 aa[4];
#pragma unroll
                for (int i = 0; i < 4; i++)
                    aa[i] = *(const uint4*)(Ab + ((kpp * 2 + hh) * 8 + wm * 4 + i) * 128 + lane * 4);
#pragma unroll
                for (int i = 0; i < 4; i++)
#pragma unroll
                    for (int j = 0; j < 8; j++)
                        mma8(acc[i][j], aa[i],
                             hh ? bb[j].z : bb[j].x,
                             hh ? bb[j].w : bb[j].y);
            }
        }

        if (more) {
            float* Ab2 = Asm + (buf ^ 1) * 4096;
            float* Bb2 = Bsm + (buf ^ 1) * 8192;
#pragma unroll
            for (int p = 0; p < 4; p++) {
                Ab2[Abase + p * 256 + 0] = pa[p].x; Ab2[Abase + p * 256 + 4] = pa[p].y;
                Ab2[Abase + p * 256 + 8] = pa[p].z; Ab2[Abase + p * 256 + 12] = pa[p].w;
            }
#pragma unroll
            for (int p = 0; p < 8; p++) {
                Bb2[Bbase + p * 512 + 0] = pb[p].x; Bb2[Bbase + p * 512 + 4] = pb[p].y;
                Bb2[Bbase + p * 512 + 8] = pb[p].z; Bb2[Bbase + p * 512 + 12] = pb[p].w;
            }
        }
        __syncthreads();
        buf ^= 1;
    }

#pragma unroll
    for (int i = 0; i < 4; i++) {
        int gm = m0 + (wm * 4 + i) * 16 + (lane >> 2);
#pragma unroll
        for (int j = 0; j < 8; j++) {
            int gn = n0 + (wn * 8 + j) * 8 + 2 * (lane & 3);
            size_t o0 = (size_t)gm * N + gn;
            size_t o1 = (size_t)(gm + 8) * N + gn;
            if (EPI == 0) {
                *(float2*)(C + o0) = make_float2(acc[i][j][0], acc[i][j][1]);
                *(float2*)(C + o1) = make_float2(acc[i][j][2], acc[i][j][3]);
            } else {
                int b0 = gm >> 11, b1 = (gm + 8) >> 11;
                float2 h0 = *(const float2*)(hid + o0);
                float2 h1 = *(const float2*)(hid + o1);
                float2 g0 = *(const float2*)(g_mod + b0 * D3c + 2 * Dc + gn);
                float2 g1 = *(const float2*)(g_mod + b1 * D3c + 2 * Dc + gn);
                *(float2*)(C + o0) = make_float2(fmaf(g0.x, acc[i][j][0], h0.x),
                                                 fmaf(g0.y, acc[i][j][1], h0.y));
                *(float2*)(C + o1) = make_float2(fmaf(g1.x, acc[i][j][2], h1.x),
                                                 fmaf(g1.y, acc[i][j][3], h1.y));
            }
        }
    }
}

// ====== per-head RMSNorm + mixed RoPE =========================================
__global__ void __launch_bounds__(256)
k_qknorm_rope(const float* __restrict__ cos1d, const float* __restrict__ sin1d,
              const float* __restrict__ rope3d,
              const float* __restrict__ qn, const float* __restrict__ kn,
              const int* __restrict__ mp) {
    int warp = threadIdx.x >> 5, lane = threadIdx.x & 31;
    int v  = blockIdx.x * 8 + warp;
    int bl = v / 24, r = v % 24;
    int b = bl >> 11, l = bl & 2047;

    float* ptr; const float* w;
    if (r < Hc) { ptr = g_qkv + (size_t)bl * QKVN + r * Dhc;               w = qn; }
    else        { ptr = g_qkv + (size_t)bl * QKVN + 2048 + (r - Hc) * Dhc; w = kn; }

    float val[4];
    float ss = 0.f;
#pragma unroll
    for (int i = 0; i < 4; i++) { val[i] = ptr[lane + 32 * i]; ss = fmaf(val[i], val[i], ss); }
#pragma unroll
    for (int o = 16; o; o >>= 1) ss += __shfl_xor_sync(0xffffffffu, ss, o);
    float inv = rsqrtf(ss * (1.f / Dhc) + EPSc);
#pragma unroll
    for (int i = 0; i < 4; i++) val[i] *= inv * w[lane + 32 * i];

    bool is64 = (mp[1] == 0);
    bool in_full = false, in_img = false; int rel = 0;
#pragma unroll
    for (int m = 0; m < 2; m++) {
        int off, ln;
        if (is64) { off = mp[(b * 4 + m * 2) * 2]; ln = mp[(b * 4 + m * 2 + 1) * 2]; }
        else      { off = mp[b * 4 + m * 2];       ln = mp[b * 4 + m * 2 + 1]; }
        int seg_end = off + max(ln, 1);
        if (l >= off && l < seg_end) in_full = true;
        if (l >= off + 1 && l < off + ln) { in_img = true; rel += l - (off + 1); }
    }
    bool text = !in_full;
    bool img  = in_img && (rel < 1024);
    rel = min(max(rel, 0), 1023);

    float out[4];
    if (text) {
#pragma unroll
        for (int i = 0; i < 4; i++) {
            int d = lane + 32 * i;
            float c = cos1d[l * Dhc + d], s = sin1d[l * Dhc + d];
            float rot = (i < 2) ? -val[i ^ 2] : val[i ^ 2];
            out[i] = fmaf(val[i], c, rot * s);
        }
    } else {
#pragma unroll
        for (int i = 0; i < 4; i++) {
            int d = lane + 32 * i; int p = d >> 1; int jj = d & 1;
            float partner = __shfl_xor_sync(0xffffffffu, val[i], 1);
            float q0 = jj ? partner : val[i];
            float q1 = jj ? val[i] : partner;
            const float* R = rope3d + ((size_t)rel * 64 + p) * 4;
            float oimg = fmaf(q0, R[jj], q1 * R[2 + jj]);
            out[i] = img ? oimg : val[i];
        }
    }
#pragma unroll
    for (int i = 0; i < 4; i++) ptr[lane + 32 * i] = out[i];
}

// ====== flash attention, tf32 mma.sync ========================================
// CTA: 128 q-rows x 1 head. 8 warps (4 m x 2 n). kv-tile = 64.
// smem floats: Qf[16384] Kf[8192] Vf[8192] Pf[8192] red[512]
#define FSMEM ((16384 + 8192 + 8192 + 8192 + 512) * 4)

__global__ void __launch_bounds__(256, 1)
k_flash(float* __restrict__ go) {
    extern __shared__ float sm[];
    float*  Qf  = sm;
    float*  Kf  = sm + 16384;
    float*  Vf  = sm + 24576;
    float*  Pf  = sm + 32768;
    float2* red = (float2*)(sm + 40960);   // [wn][128] (rowmax, rowsum)

    int t = threadIdx.x, l = t & 31, wid = t >> 5;
    int lo = l & 3, lr = l >> 2;
    int wm = wid >> 1, wn = wid & 1;
    int q0 = blockIdx.x << 7;
    int h  = blockIdx.y, b = blockIdx.z;
    int kh = h >> 1;
    const float SC = 0.08838834764831845f;   // 1/sqrt(128)

    // ---- load Q (once) into A-fragment layout, tf32 ----
    {
        const float* qb = g_qkv + (size_t)(b * Lc + q0) * QKVN + h * Dhc;
#pragma unroll
        for (int i = 0; i < 16; i++) {
            int idx = t + (i << 8);
            int row = idx >> 5, c4 = (idx & 31) << 2;
            float4 v = *(const float4*)(qb + (size_t)row * QKVN + c4);
            int base = ((c4 >> 3) * 8 + (row >> 4)) * 128 + (row & 7) * 16
                     + ((row >> 3) & 1) + ((c4 >> 2) & 1) * 2;
            Qf[base + 0]  = to_tf32(v.x); Qf[base + 4]  = to_tf32(v.y);
            Qf[base + 8]  = to_tf32(v.z); Qf[base + 12] = to_tf32(v.w);
        }
    }
    // ---- load K(0), V(0) ----
    {
#pragma unroll
        for (int i = 0; i < 8; i++) {
            int idx = t + (i << 8);
            int n = idx >> 5, c4 = (idx & 31) << 2;
            float4 v = *(const float4*)(g_qkv + (size_t)(b * Lc + n) * QKVN + 2048 + kh * Dhc + c4);
            int base = ((c4 >> 4) * 8 + (n >> 3)) * 128 + (n & 7) * 16
                     + ((c4 >> 2) & 1) + ((c4 >> 3) & 1) * 2;
            Kf[base + 0] = to_tf32(v.x); Kf[base + 4] = to_tf32(v.y);
            Kf[base + 8] = to_tf32(v.z); Kf[base + 12] = to_tf32(v.w);
        }
#pragma unroll
        for (int i = 0; i < 8; i++) {
            int idx = t + (i << 8);
            int kv = idx >> 5, c4 = (idx & 31) << 2;
            float4 v = *(const float4*)(g_qkv + (size_t)(b * Lc + kv) * QKVN + 3072 + kh * Dhc + c4);
            int base = ((kv >> 4) * 16 + (c4 >> 3)) * 128 + (c4 & 7) * 16
                     + (kv & 3) * 4 + ((kv >> 2) & 1) + ((kv >> 3) & 1) * 2;
            Vf[base + 0]  = to_tf32(v.x); Vf[base + 16] = to_tf32(v.y);
            Vf[base + 32] = to_tf32(v.z); Vf[base + 48] = to_tf32(v.w);
        }
    }
    __syncthreads();

    float accO[2][8][4];
    float m_run[4], l_run[4];
#pragma unroll
    for (int i = 0; i < 2; i++)
#pragma unroll
        for (int j = 0; j < 8; j++)
#pragma unroll
            for (int c = 0; c < 4; c++) accO[i][j][c] = 0.f;
#pragma unroll
    for (int r = 0; r < 4; r++) { m_run[r] = -1e30f; l_run[r] = 0.f; }

    for (int kt = 0; kt < 32; kt++) {
        bool more = (kt + 1 < 32);
        // prefetch K(t+1)
        float4 pre[8];
        if (more) {
#pragma unroll
            for (int i = 0; i < 8; i++) {
                int idx = t + (i << 8);
                int n = idx >> 5, c4 = (idx & 31) << 2;
                pre[i] = *(const float4*)(g_qkv + (size_t)(b * Lc + (kt + 1) * 64 + n) * QKVN
                                          + 2048 + kh * Dhc + c4);
            }
        }

        // ---- S = Q @ K^T (warp tile 32x32) ----
        float accS[2][4][4];
#pragma unroll
        for (int i = 0; i < 2; i++)
#pragma unroll
            for (int j = 0; j < 4; j++)
#pragma unroll
                for (int c = 0; c < 4; c++) accS[i][j][c] = 0.f;
#pragma unroll
        for (int kp = 0; kp < 8; kp++) {
            uint4 bb[4];
#pragma unroll
            for (int nj = 0; nj < 4; nj++)
                bb[nj] = *(const uint4*)&Kf[(kp * 8 + wn * 4 + nj) * 128 + l * 4];
#pragma unroll
            for (int hh = 0; hh < 2; hh++) {
                uint4 aa[2];
#pragma unroll
                for (int mi = 0; mi < 2; mi++)
                    aa[mi] = *(const uint4*)&Qf[((kp * 2 + hh) * 8 + wm * 2 + mi) * 128 + l * 4];
#pragma unroll
                for (int mi = 0; mi < 2; mi++)
#pragma unroll
                    for (int nj = 0; nj < 4; nj++)
                        mma8(accS[mi][nj], aa[mi],
                             hh ? bb[nj].z : bb[nj].x,
                             hh ? bb[nj].w : bb[nj].y);
            }
        }

        // ---- softmax part 1: scale, warp-partial max, exp, partial sum ----
        float pm[4], ps[4];
#pragma unroll
        for (int r = 0; r < 4; r++) { pm[r] = -1e30f; ps[r] = 0.f; }
#pragma unroll
        for (int mi = 0; mi < 2; mi++)
#pragma unroll
            for (int nj = 0; nj < 4; nj++)
#pragma unroll
                for (int c = 0; c < 4; c++) {
                    float v = accS[mi][nj][c] * SC;
                    accS[mi][nj][c] = v;
                    int ri = mi * 2 + (c >> 1);
                    pm[ri] = fmaxf(pm[ri], v);
                }
#pragma unroll
        for (int r = 0; r < 4; r++) {
            pm[r] = fmaxf(pm[r], __shfl_xor_sync(0xffffffffu, pm[r], 1));
            pm[r] = fmaxf(pm[r], __shfl_xor_sync(0xffffffffu, pm[r], 2));
        }
#pragma unroll
        for (int mi = 0; mi < 2; mi++)
#pragma unroll
            for (int nj = 0; nj < 4; nj++)
#pragma unroll
                for (int c = 0; c < 4; c++) {
                    int ri = mi * 2 + (c >> 1);
                    float p = __expf(accS[mi][nj][c] - pm[ri]);
                    accS[mi][nj][c] = p;
                    ps[ri] += p;
                }
#pragma unroll
        for (int r = 0; r < 4; r++) {
            ps[r] += __shfl_xor_sync(0xffffffffu, ps[r], 1);
            ps[r] += __shfl_xor_sync(0xffffffffu, ps[r], 2);
        }
        if (lo == 0) {
#pragma unroll
            for (int mi = 0; mi < 2; mi++)
#pragma unroll
                for (int rb = 0; rb < 2; rb++) {
                    int grow = wm * 32 + mi * 16 + lr + 8 * rb;
                    red[wn * 128 + grow] = make_float2(pm[mi * 2 + rb], ps[mi * 2 + rb]);
                }
        }
        __syncthreads();   // red ready; all warps done reading Kf

        // ---- merge stats across wn-halves, correct O, store Pf ----
        float cf[4], corr[4];
#pragma unroll
        for (int mi = 0; mi < 2; mi++)
#pragma unroll
            for (int rb = 0; rb < 2; rb++) {
                int ri = mi * 2 + rb;
                int grow = wm * 32 + mi * 16 + lr + 8 * rb;
                float2 f0 = red[grow], f1 = red[128 + grow];
                float mnew = fmaxf(m_run[ri], fmaxf(f0.x, f1.x));
                float gsum = f0.y * __expf(f0.x - mnew) + f1.y * __expf(f1.x - mnew);
                corr[ri] = __expf(m_run[ri] - mnew);
                l_run[ri] = l_run[ri] * corr[ri] + gsum;
                m_run[ri] = mnew;
                cf[ri] = __expf(pm[ri] - mnew);
            }
#pragma unroll
        for (int mi = 0; mi < 2; mi++)
#pragma unroll
            for (int nj = 0; nj < 8; nj++)
#pragma unroll
                for (int c = 0; c < 4; c++)
                    accO[mi][nj][c] *= corr[mi * 2 + (c >> 1)];
        // Pf store (A-frag layout, m=q row local, k=kv local)
#pragma unroll
        for (int mi = 0; mi < 2; mi++)
#pragma unroll
            for (int nj = 0; nj < 4; nj++)
#pragma unroll
                for (int c = 0; c < 4; c++) {
                    int rb = c >> 1, cb = c & 1;
                    int addr = ((wn * 4 + nj) * 8 + wm * 2 + mi) * 128
                             + lr * 16 + rb + (2 * (lo & 1) + cb) * 4 + (lo >> 1) * 2;
                    Pf[addr] = to_tf32(accS[mi][nj][c] * cf[mi * 2 + rb]);
                }
        // store prefetched K(t+1)
        if (more) {
#pragma unroll
            for (int i = 0; i < 8; i++) {
                int idx = t + (i << 8);
                int n = idx >> 5, c4 = (idx & 31) << 2;
                int base = ((c4 >> 4) * 8 + (n >> 3)) * 128 + (n & 7) * 16
                         + ((c4 >> 2) & 1) + ((c4 >> 3) & 1) * 2;
                Kf[base + 0] = to_tf32(pre[i].x); Kf[base + 4]  = to_tf32(pre[i].y);
                Kf[base + 8] = to_tf32(pre[i].z); Kf[base + 12] = to_tf32(pre[i].w);
            }
            // prefetch V(t+1)
#pragma unroll
            for (int i = 0; i < 8; i++) {
                int idx = t + (i << 8);
                int kv = idx >> 5, c4 = (idx & 31) << 2;
                pre[i] = *(const float4*)(g_qkv + (size_t)(b * Lc + (kt + 1) * 64 + kv) * QKVN
                                          + 3072 + kh * Dhc + c4);
            }
        }
        __syncthreads();   // Pf ready (Kf(t+1) ready for next iter)

        // ---- O += P @ V (warp tile 32x64) ----
#pragma unroll
        for (int kp = 0; kp < 4; kp++) {
            uint4 bb[8];
#pragma unroll
            for (int nj = 0; nj < 8; nj++)
                bb[nj] = *(const uint4*)&Vf[(kp * 16 + wn * 8 + nj) * 128 + l * 4];
#pragma unroll
            for (int hh = 0; hh < 2; hh++) {
                uint4 aa[2];
#pragma unroll
                for (int mi = 0; mi < 2; mi++)
                    aa[mi] = *(const uint4*)&Pf[((kp * 2 + hh) * 8 + wm * 2 + mi) * 128 + l * 4];
#pragma unroll
                for (int mi = 0; mi < 2; mi++)
#pragma unroll
                    for (int nj = 0; nj < 8; nj++)
                        mma8(accO[mi][nj], aa[mi],
                             hh ? bb[nj].z : bb[nj].x,
                             hh ? bb[nj].w : bb[nj].y);
            }
        }
        __syncthreads();   // all reads of Vf / Pf done

        // store prefetched V(t+1)
        if (more) {
#pragma unroll
            for (int i = 0; i < 8; i++) {
                int idx = t + (i << 8);
                int kv = idx >> 5, c4 = (idx & 31) << 2;
                int base = ((kv >> 4) * 16 + (c4 >> 3)) * 128 + (c4 & 7) * 16
                         + (kv & 3) * 4 + ((kv >> 2) & 1) + ((kv >> 3) & 1) * 2;
                Vf[base + 0]  = to_tf32(pre[i].x); Vf[base + 16] = to_tf32(pre[i].y);
                Vf[base + 32] = to_tf32(pre[i].z); Vf[base + 48] = to_tf32(pre[i].w);
            }
        }
    }

    // ---- epilogue: O /= l, write (tf32 for O-projection GEMM) ----
    float inv[4];
#pragma unroll
    for (int r = 0; r < 4; r++) inv[r] = 1.f / l_run[r];
#pragma unroll
    for (int mi = 0; mi < 2; mi++)
#pragma unroll
        for (int nj = 0; nj < 8; nj++) {
            int col = h * Dhc + wn * 64 + nj * 8 + 2 * lo;
#pragma unroll
            for (int rb = 0; rb < 2; rb++) {
                int row = q0 + wm * 32 + mi * 16 + lr + 8 * rb;
                float iv = inv[mi * 2 + rb];
                *(float2*)(go + (size_t)(b * Lc + row) * Dc + col) =
                    make_float2(to_tf32(accO[mi][nj][rb * 2 + 0] * iv),
                                to_tf32(accO[mi][nj][rb * 2 + 1] * iv));
            }
        }
}

// ================================ host ========================================
extern "C" void kernel_launch(void* const* d_in, const int* in_sizes, int n_in,
                              void* d_out, int out_size) {
    const float* hidden = (const float*)d_in[0];
    const float* temb   = (const float*)d_in[1];
    const float* w_ln   = (const float*)d_in[2];
    const float* w_mod  = (const float*)d_in[3];
    const float* b_mod  = (const float*)d_in[4];
    const float* wq     = (const float*)d_in[5];
    const float* wk     = (const float*)d_in[6];
    const float* wv     = (const float*)d_in[7];
    const float* wo     = (const float*)d_in[8];
    const float* qn     = (const float*)d_in[9];
    const float* kn     = (const float*)d_in[10];
    const float* cos1   = (const float*)d_in[11];
    const float* sin1   = (const float*)d_in[12];
    const float* rope3  = (const float*)d_in[13];
    const int*   mpos   = (const int*)d_in[14];
    float* out = (float*)d_out;

    void *pxm, *pqkv, *po, *pwT, *pwoT;
    cudaGetSymbolAddress(&pxm,  g_xm);
    cudaGetSymbolAddress(&pqkv, g_qkv);
    cudaGetSymbolAddress(&po,   g_o);
    cudaGetSymbolAddress(&pwT,  g_wT);
    cudaGetSymbolAddress(&pwoT, g_woT);

    cudaFuncSetAttribute(k_mma<0>, cudaFuncAttributeMaxDynamicSharedMemorySize, MMASMEM);
    cudaFuncSetAttribute(k_mma<1>, cudaFuncAttributeMaxDynamicSharedMemorySize, MMASMEM);
    cudaFuncSetAttribute(k_flash, cudaFuncAttributeMaxDynamicSharedMemorySize, FSMEM);

    k_mod<<<dim3(D3c / 256, Bc), 256>>>(temb, w_mod, b_mod);
    k_rmsmod<<<Bc * Lc, 256>>>(hidden, w_ln);

    k_transpose<<<dim3(Dc / 32, Dc / 32), dim3(32, 8)>>>(wq, (float*)pwT, Dc, Dc);
    k_transpose<<<dim3(1024 / 32, Dc / 32), dim3(32, 8)>>>(wk, (float*)pwT + (size_t)2048 * Dc, Dc, 1024);
    k_transpose<<<dim3(1024 / 32, Dc / 32), dim3(32, 8)>>>(wv, (float*)pwT + (size_t)3072 * Dc, Dc, 1024);
    k_transpose<<<dim3(Dc / 32, Dc / 32), dim3(32, 8)>>>(wo, (float*)pwoT, Dc, Dc);

    k_mma<0><<<dim3(QKVN / 256, (Bc * Lc) / 128), 256, MMASMEM>>>(
        (const float*)pxm, (const float*)pwT, (float*)pqkv, QKVN, Dc, nullptr);

    k_qknorm_rope<<<(Bc * Lc * (Hc + KVHc)) / 8, 256>>>(cos1, sin1, rope3, qn, kn, mpos);

    k_flash<<<dim3(Lc / 128, Hc, Bc), 256, FSMEM>>>((float*)po);

    k_mma<1><<<dim3(Dc / 256, (Bc * Lc) / 128), 256, MMASMEM>>>(
        (const float*)po, (const float*)pwoT, out, Dc, Dc, hidden);
}